// round 11
// baseline (speedup 1.0000x reference)
#include <cuda_runtime.h>
#include <cuda_bf16.h>
#include <cstdint>

// Problem constants
#define S_DIM 8192
#define B_DIM 8192
#define ENC 256
#define C_DIM 25
#define K_RANK 25   // 0-based rank -> 26th smallest

// ------------------------------------------------------------------
// Scratch (device globals; allocation-free per harness rules)
// ------------------------------------------------------------------
__device__ __align__(256) float g_d2[(size_t)S_DIM * B_DIM];            // 268 MB
__device__ __align__(256) float g_ehi[(size_t)B_DIM * ENC];             // tf32(e)
__device__ __align__(256) float g_qhi[(size_t)S_DIM * ENC];             // gathered tf32(q)
__device__ __align__(256) __nv_bfloat16 g_ecA[(size_t)B_DIM * 2 * ENC]; // [qh16 | ql16]
__device__ __align__(256) __nv_bfloat16 g_ecB[(size_t)B_DIM * 2 * ENC]; // [el16 | eh16]
__device__ __align__(256) __nv_bfloat16 g_qcA[(size_t)S_DIM * 2 * ENC]; // gathered corr-A
__device__ __align__(256) unsigned int g_cbmin[(size_t)S_DIM * 32];     // per-row col-block mins
__device__ float g_e2[B_DIM];
__device__ float g_q2[S_DIM];
__device__ float g_maxg[B_DIM];
__device__ unsigned char g_grp[B_DIM];

// ------------------------------------------------------------------
// Base-ISA PTX helpers (harness compiles via compute_103: NO 'a' features)
// ------------------------------------------------------------------
__device__ __forceinline__ uint32_t smem_u32(const void* p) {
    uint32_t a;
    asm("{ .reg .u64 t; cvta.to.shared.u64 t, %1; cvt.u32.u64 %0, t; }"
        : "=r"(a) : "l"(p));
    return a;
}
__device__ __forceinline__ float tf32_rn(float x) {
    uint32_t u;
    asm("cvt.rna.tf32.f32 %0, %1;" : "=r"(u) : "f"(x));
    return __uint_as_float(u);
}
__device__ __forceinline__ void cp16(uint32_t dst, const void* src) {
    asm volatile("cp.async.cg.shared.global [%0], [%1], 16;" :: "r"(dst), "l"(src));
}
__device__ __forceinline__ void ldsm4(uint32_t* r, uint32_t addr) {
    asm volatile("ldmatrix.sync.aligned.m8n8.x4.shared.b16 {%0,%1,%2,%3}, [%4];"
                 : "=r"(r[0]), "=r"(r[1]), "=r"(r[2]), "=r"(r[3]) : "r"(addr));
}
__device__ __forceinline__ void mma_tf32(float* c, const uint32_t* a, const uint32_t* b) {
    asm volatile(
        "mma.sync.aligned.m16n8k8.row.col.f32.tf32.tf32.f32 "
        "{%0,%1,%2,%3}, {%4,%5,%6,%7}, {%8,%9}, {%0,%1,%2,%3};"
        : "+f"(c[0]), "+f"(c[1]), "+f"(c[2]), "+f"(c[3])
        : "r"(a[0]), "r"(a[1]), "r"(a[2]), "r"(a[3]), "r"(b[0]), "r"(b[1]));
}
__device__ __forceinline__ void mma_bf16(float* c, const uint32_t* a, const uint32_t* b) {
    asm volatile(
        "mma.sync.aligned.m16n8k16.row.col.f32.bf16.bf16.f32 "
        "{%0,%1,%2,%3}, {%4,%5,%6,%7}, {%8,%9}, {%0,%1,%2,%3};"
        : "+f"(c[0]), "+f"(c[1]), "+f"(c[2]), "+f"(c[3])
        : "r"(a[0]), "r"(a[1]), "r"(a[2]), "r"(a[3]), "r"(b[0]), "r"(b[1]));
}
#define SWZ(o) ((o) ^ (((o) >> 3) & 0x70))

// ------------------------------------------------------------------
// Kernel 0: init per-row block-min table to UINT_MAX
// ------------------------------------------------------------------
__global__ void init_cbmin() {
    int i = blockIdx.x * blockDim.x + threadIdx.x;
    uint4 ff = make_uint4(0xFFFFFFFFu, 0xFFFFFFFFu, 0xFFFFFFFFu, 0xFFFFFFFFu);
    reinterpret_cast<uint4*>(g_cbmin)[i] = ff;   // 65536 uint4 = 256x256
}

// ------------------------------------------------------------------
// Kernel 1: e2, argmax/max, tf32 + bf16 splits.  One block per b-row.
// ------------------------------------------------------------------
__global__ void prep_kernel(const float* __restrict__ enc,
                            const float* __restrict__ cat) {
    int b = blockIdx.x;
    int t = threadIdx.x;

    float v  = enc[(size_t)b * ENC + t];
    float hi = tf32_rn(v);
    float lo = v - hi;
    g_ehi[(size_t)b * ENC + t] = hi;
    __nv_bfloat16 h16 = __float2bfloat16(hi);
    __nv_bfloat16 l16 = __float2bfloat16(lo);
    g_ecA[(size_t)b * 2 * ENC + t]       = h16;
    g_ecA[(size_t)b * 2 * ENC + ENC + t] = l16;
    g_ecB[(size_t)b * 2 * ENC + t]       = l16;
    g_ecB[(size_t)b * 2 * ENC + ENC + t] = h16;

    float sq = v * v;
    #pragma unroll
    for (int o = 16; o > 0; o >>= 1) sq += __shfl_xor_sync(0xFFFFFFFFu, sq, o);

    __shared__ float ws[8];
    if ((t & 31) == 0) ws[t >> 5] = sq;
    __syncthreads();
    if (t == 0) {
        float s = 0.f;
        #pragma unroll
        for (int i = 0; i < 8; i++) s += ws[i];
        g_e2[b] = s;
    }

    if (t < 32) {
        float mv = -1e30f;
        int   mi = 0x7FFFFFFF;
        if (t < C_DIM) { mv = cat[(size_t)b * C_DIM + t]; mi = t; }
        #pragma unroll
        for (int o = 16; o > 0; o >>= 1) {
            float ov = __shfl_xor_sync(0xFFFFFFFFu, mv, o);
            int   oi = __shfl_xor_sync(0xFFFFFFFFu, mi, o);
            if (ov > mv || (ov == mv && oi < mi)) { mv = ov; mi = oi; }
        }
        if (t == 0) { g_maxg[b] = mv; g_grp[b] = (unsigned char)mi; }
    }
}

// ------------------------------------------------------------------
// Kernel 2: gather q rows (tf32 + corrA) + q2
// ------------------------------------------------------------------
__global__ void gather_kernel(const int* __restrict__ idxs) {
    int s = blockIdx.x, t = threadIdx.x;   // 64 threads
    int idx = idxs[s];
    const float4* sh = reinterpret_cast<const float4*>(&g_ehi[(size_t)idx * ENC]);
    float4* dh = reinterpret_cast<float4*>(&g_qhi[(size_t)s * ENC]);
    dh[t] = sh[t];
    const uint4* sc = reinterpret_cast<const uint4*>(&g_ecA[(size_t)idx * 2 * ENC]);
    uint4* dc = reinterpret_cast<uint4*>(&g_qcA[(size_t)s * 2 * ENC]);
    dc[t] = sc[t];
    if (t == 0) g_q2[s] = g_e2[idx];
}

// ------------------------------------------------------------------
// Kernel 3: mixed tf32 + bf16 GEMM -> d2.
// 512 threads, warp grid 2(M) x 8(N), warp tile 64x32:
// R9's ldsm/MMA ratio (12/32) with R10's warp count.
// ------------------------------------------------------------------
#define BM 128
#define BN 256
#define NCHUNK 8
#define NTHREADS 512
#define AF32_OFF 0
#define ACOR_OFF (128 * 128)                    // 16 KB
#define BF32_OFF (2 * 128 * 128)                // 32 KB
#define BCOR_OFF (BF32_OFF + 256 * 128)         // +32 KB
#define STAGE    (BCOR_OFF + 256 * 128)         // 96 KB
#define GEMM_SMEM (2 * STAGE)                   // 192 KB

__device__ __forceinline__ void load_stage(uint32_t st, int brow, int bcol,
                                           int c, int tid) {
    const char* qcA = reinterpret_cast<const char*>(g_qcA);
    const char* ecB = reinterpret_cast<const char*>(g_ecB);
    #pragma unroll
    for (int it = 0; it < 2; ++it) {
        int i = tid + it * NTHREADS;            // 0..1023 : 128 rows x 8 chunks
        int r = i >> 3, ch = i & 7;
        uint32_t off = SWZ((uint32_t)(r * 128 + ch * 16));
        cp16(st + AF32_OFF + off, g_qhi + (size_t)(brow + r) * ENC + c * 32 + ch * 4);
        cp16(st + ACOR_OFF + off, qcA + (size_t)(brow + r) * 1024 + c * 128 + ch * 16);
    }
    #pragma unroll
    for (int it = 0; it < 4; ++it) {
        int i = tid + it * NTHREADS;            // 0..2047 : 256 rows x 8 chunks
        int r = i >> 3, ch = i & 7;
        uint32_t off = SWZ((uint32_t)(r * 128 + ch * 16));
        cp16(st + BF32_OFF + off, g_ehi + (size_t)(bcol + r) * ENC + c * 32 + ch * 4);
        cp16(st + BCOR_OFF + off, ecB + (size_t)(bcol + r) * 1024 + c * 128 + ch * 16);
    }
    asm volatile("cp.async.commit_group;" ::: "memory");
}

__global__ __launch_bounds__(NTHREADS, 1)
void dist_gemm_mma() {
    extern __shared__ char dsm_raw[];
    __shared__ float e2s[BN];
    __shared__ float q2s[BM];

    const int tid    = threadIdx.x;
    const int lane   = tid & 31;
    const int wid    = tid >> 5;
    const int warp_m = wid & 1;        // 2 warps over M (64 rows each)
    const int warp_n = wid >> 1;       // 8 warps over N (32 cols each)
    const int brow   = blockIdx.y * BM;
    const int bcol   = blockIdx.x * BN;

    const uint32_t dsm = smem_u32(dsm_raw);

    for (int i = tid; i < BN; i += NTHREADS) e2s[i] = g_e2[bcol + i];
    for (int i = tid; i < BM; i += NTHREADS) q2s[i] = g_q2[brow + i];

    float acc[4][4][4];
    #pragma unroll
    for (int im = 0; im < 4; im++)
        #pragma unroll
        for (int j = 0; j < 4; j++)
            #pragma unroll
            for (int v = 0; v < 4; v++) acc[im][j][v] = 0.f;

    const int a_row = warp_m * 64 + (lane & 15);                       // + im*16
    const int a_kb  = (lane >> 4) << 4;                                // + ks*32
    const int b_row = warp_n * 32 + ((lane >> 4) << 3) + (lane & 7);   // + jn*16
    const int b_kb  = ((lane >> 3) & 1) << 4;                          // + ks*32

    load_stage(dsm,         brow, bcol, 0, tid);
    load_stage(dsm + STAGE, brow, bcol, 1, tid);

    #pragma unroll
    for (int c = 0; c < NCHUNK; ++c) {
        if (c == NCHUNK - 1) asm volatile("cp.async.wait_group 0;" ::: "memory");
        else                 asm volatile("cp.async.wait_group 1;" ::: "memory");
        __syncthreads();

        const uint32_t st = dsm + (c & 1) * STAGE;

        #pragma unroll
        for (int ks = 0; ks < 4; ++ks) {
            uint32_t ahi[4][4], aco[4][4], bhi[4][2], bco[4][2];
            #pragma unroll
            for (int im = 0; im < 4; ++im) {
                uint32_t off = SWZ((uint32_t)((a_row + im * 16) * 128 + ks * 32 + a_kb));
                ldsm4(ahi[im], st + AF32_OFF + off);
                ldsm4(aco[im], st + ACOR_OFF + off);
            }
            #pragma unroll
            for (int jn = 0; jn < 2; ++jn) {
                uint32_t off = SWZ((uint32_t)((b_row + jn * 16) * 128 + ks * 32 + b_kb));
                uint32_t rh[4], rc[4];
                ldsm4(rh, st + BF32_OFF + off);
                ldsm4(rc, st + BCOR_OFF + off);
                bhi[2 * jn][0] = rh[0]; bhi[2 * jn][1] = rh[1];
                bhi[2 * jn + 1][0] = rh[2]; bhi[2 * jn + 1][1] = rh[3];
                bco[2 * jn][0] = rc[0]; bco[2 * jn][1] = rc[1];
                bco[2 * jn + 1][0] = rc[2]; bco[2 * jn + 1][1] = rc[3];
            }
            #pragma unroll
            for (int im = 0; im < 4; ++im)
                #pragma unroll
                for (int j = 0; j < 4; ++j) {
                    mma_tf32(acc[im][j], ahi[im], bhi[j]);
                    mma_bf16(acc[im][j], aco[im], bco[j]);
                }
        }
        __syncthreads();
        if (c + 2 < NCHUNK)
            load_stage(dsm + (c & 1) * STAGE, brow, bcol, c + 2, tid);
    }

    // Epilogue: d2 = max(q2 + e2 - 2*acc, 0), plain stores, and
    // per-row min over this CTA's 256 columns -> g_cbmin[row][blockIdx.x].
    #pragma unroll
    for (int im = 0; im < 4; ++im) {
        const int r0 = warp_m * 64 + im * 16 + (lane >> 2);
        const float q2a = q2s[r0];
        const float q2b = q2s[r0 + 8];
        uint32_t mna = 0xFFFFFFFFu, mnb = 0xFFFFFFFFu;
        #pragma unroll
        for (int j = 0; j < 4; ++j) {
            const int cl = warp_n * 32 + j * 8 + 2 * (lane & 3);
            const float e0 = e2s[cl], e1 = e2s[cl + 1];
            float2 oa, ob;
            oa.x = fmaxf(fmaf(-2.f, acc[im][j][0], q2a + e0), 0.f);
            oa.y = fmaxf(fmaf(-2.f, acc[im][j][1], q2a + e1), 0.f);
            ob.x = fmaxf(fmaf(-2.f, acc[im][j][2], q2b + e0), 0.f);
            ob.y = fmaxf(fmaf(-2.f, acc[im][j][3], q2b + e1), 0.f);
            mna = min(mna, min(__float_as_uint(oa.x), __float_as_uint(oa.y)));
            mnb = min(mnb, min(__float_as_uint(ob.x), __float_as_uint(ob.y)));
            *reinterpret_cast<float2*>(&g_d2[(size_t)(brow + r0) * B_DIM + bcol + cl]) = oa;
            *reinterpret_cast<float2*>(&g_d2[(size_t)(brow + r0 + 8) * B_DIM + bcol + cl]) = ob;
        }
        // combine the 4 lanes (lane&3) that share each row
        mna = min(mna, __shfl_xor_sync(0xFFFFFFFFu, mna, 1));
        mna = min(mna, __shfl_xor_sync(0xFFFFFFFFu, mna, 2));
        mnb = min(mnb, __shfl_xor_sync(0xFFFFFFFFu, mnb, 1));
        mnb = min(mnb, __shfl_xor_sync(0xFFFFFFFFu, mnb, 2));
        if ((lane & 3) == 0) {
            atomicMin(&g_cbmin[(size_t)(brow + r0) * 32 + blockIdx.x], mna);
            atomicMin(&g_cbmin[(size_t)(brow + r0 + 8) * 32 + blockIdx.x], mnb);
        }
    }
}

// ------------------------------------------------------------------
// Kernel 4 (v8): bound-from-GEMM select. Exact. (unchanged from R9)
// ------------------------------------------------------------------
#define CAND_CAP 2048

__global__ __launch_bounds__(256)
void select_kernel(const int* __restrict__ idxs, float* __restrict__ out) {
    const int s    = blockIdx.x;
    const int tid  = threadIdx.x;
    const int lane = tid & 31;
    const int wid  = tid >> 5;

    __shared__ uint32_t cand_v[CAND_CAP];     // 8 KB
    __shared__ uint32_t cand_i[CAND_CAP];     // 8 KB
    __shared__ uint32_t wred[8];
    __shared__ uint32_t sh_m;
    __shared__ uint32_t sh_B;
    __shared__ uint32_t sh_kbits;
    __shared__ int counts[C_DIM];

    // Bound from GEMM by-product: max of 32 block mins
    if (wid == 0) {
        uint32_t b = g_cbmin[(size_t)s * 32 + lane];
        #pragma unroll
        for (int o = 16; o > 0; o >>= 1)
            b = max(b, __shfl_xor_sync(0xFFFFFFFFu, b, o));
        if (lane == 0) sh_B = b;
    }

    // Load row into registers (coalesced uint4)
    const uint4* row4 = reinterpret_cast<const uint4*>(g_d2 + (size_t)s * B_DIM);
    uint4 v[8];
    #pragma unroll
    for (int k = 0; k < 8; k++) v[k] = row4[tid + k * 256];

    if (tid == 0) sh_m = 0;
    __syncthreads();
    uint32_t B = sh_B;

    // count of values strictly below X (fallback path only)
    auto count_lt = [&](uint32_t X) -> int {
        int c = 0;
        #pragma unroll
        for (int k = 0; k < 8; k++)
            c += (int)(v[k].x < X) + (int)(v[k].y < X) +
                 (int)(v[k].z < X) + (int)(v[k].w < X);
        #pragma unroll
        for (int o = 16; o > 0; o >>= 1)
            c += __shfl_xor_sync(0xFFFFFFFFu, c, o);
        if (lane == 0) wred[wid] = (uint32_t)c;
        __syncthreads();
        int t = 0;
        #pragma unroll
        for (int w = 0; w < 8; w++) t += (int)wred[w];
        __syncthreads();
        return t;
    };

    // Collect directly; expected m ~ 130 on first pass.
    int m = 0;
    bool direct = false;
    uint32_t direct_kbits = 0;
    for (int attempt = 0; attempt < 72; ++attempt) {
        #pragma unroll
        for (int k = 0; k < 8; k++) {
            uint32_t vv[4] = {v[k].x, v[k].y, v[k].z, v[k].w};
            #pragma unroll
            for (int j = 0; j < 4; j++) {
                if (vv[j] < B) {
                    uint32_t p = atomicAdd(&sh_m, 1u);
                    if (p < CAND_CAP) {
                        cand_v[p] = vv[j];
                        cand_i[p] = 4u * (uint32_t)(tid + k * 256) + (uint32_t)j;
                    }
                }
            }
        }
        __syncthreads();
        m = (int)sh_m;
        if (m >= 26 && m <= CAND_CAP) break;

        if (m < 26) {
            B += (1u << 20);
            if (B >= 0x7F800000u) B = 0x7F800001u;
        } else {
            // m > CAP: binary-search a tighter bound (pathological)
            uint32_t lo = 0;
            int cnt = m;
            while (cnt > CAND_CAP) {
                uint32_t mid = lo + ((B - lo) >> 1);
                if (mid == lo) { direct = true; direct_kbits = lo; break; }
                int c2 = count_lt(mid);
                if (c2 >= 26) { B = mid; cnt = c2; }
                else          { lo = mid; }
            }
            if (direct) break;
        }
        if (tid == 0) sh_m = 0;
        __syncthreads();
    }

    if (tid < C_DIM) counts[tid] = 0;
    __syncthreads();

    // Exact rank-25 among the m candidates
    if (!direct) {
        m = min(m, CAND_CAP);
        for (int i = tid; i < m; i += 256) {
            uint32_t vi = cand_v[i];
            int l = 0, e = 0;
            for (int j = 0; j < m; j++) {
                uint32_t vj = cand_v[j];
                l += (vj < vi);
                e += (vj == vi);
            }
            if (l <= K_RANK && K_RANK < l + e) sh_kbits = vi;
        }
    } else if (tid == 0) {
        sh_kbits = direct_kbits;
    }
    __syncthreads();
    const uint32_t kbits = sh_kbits;

    // Bincount of neighbours (v < kbits)
    if (!direct) {
        for (int i = tid; i < m; i += 256) {
            if (cand_v[i] < kbits)
                atomicAdd(&counts[g_grp[cand_i[i]]], 1);
        }
    } else {
        #pragma unroll
        for (int k = 0; k < 8; k++) {
            uint32_t vv[4] = {v[k].x, v[k].y, v[k].z, v[k].w};
            #pragma unroll
            for (int j = 0; j < 4; j++) {
                if (vv[j] < kbits)
                    atomicAdd(&counts[g_grp[4 * (tid + k * 256) + j]], 1);
            }
        }
    }
    __syncthreads();

    if (tid == 0) {
        int n = 0;
        #pragma unroll
        for (int c = 0; c < C_DIM; c++) n += counts[c];
        float inv = 1.0f / (float)n;
        float purity = 0.f;
        #pragma unroll
        for (int c = 0; c < C_DIM; c++) {
            float p = (float)counts[c] * inv;
            purity -= p * logf(p + 1e-5f);
        }
        out[s] = purity * g_maxg[idxs[s]];
    }
}

// ------------------------------------------------------------------
// Launch
// ------------------------------------------------------------------
extern "C" void kernel_launch(void* const* d_in, const int* in_sizes, int n_in,
                              void* d_out, int out_size) {
    const float* enc  = (const float*)d_in[0];
    const float* cat  = (const float*)d_in[1];
    const int*   idxs = (const int*)d_in[2];
    float* out = (float*)d_out;

    static bool attr_done = false;
    if (!attr_done) {
        cudaFuncSetAttribute(dist_gemm_mma,
                             cudaFuncAttributeMaxDynamicSharedMemorySize, GEMM_SMEM);
        attr_done = true;
    }

    init_cbmin<<<256, 256>>>();
    prep_kernel<<<B_DIM, 256>>>(enc, cat);
    gather_kernel<<<S_DIM, 64>>>(idxs);

    dim3 grid(B_DIM / BN, S_DIM / BM);
    dist_gemm_mma<<<grid, NTHREADS, GEMM_SMEM>>>();

    select_kernel<<<S_DIM, 256>>>(idxs, out);
}

// round 12
// speedup vs baseline: 1.5335x; 1.5335x over previous
#include <cuda_runtime.h>
#include <cuda_bf16.h>
#include <cstdint>

// Problem constants
#define S_DIM 8192
#define B_DIM 8192
#define ENC 256
#define C_DIM 25
#define K_RANK 25   // 0-based rank -> 26th smallest

// ------------------------------------------------------------------
// Scratch (device globals; allocation-free per harness rules)
// ------------------------------------------------------------------
__device__ __align__(256) float g_d2[(size_t)S_DIM * B_DIM];            // 268 MB
__device__ __align__(256) float g_ehi[(size_t)B_DIM * ENC];             // tf32(e)
__device__ __align__(256) float g_qhi[(size_t)S_DIM * ENC];             // gathered tf32(q), unique rows
__device__ __align__(256) __nv_bfloat16 g_ecA[(size_t)B_DIM * 2 * ENC]; // [qh16 | ql16]
__device__ __align__(256) __nv_bfloat16 g_ecB[(size_t)B_DIM * 2 * ENC]; // [el16 | eh16]
__device__ __align__(256) __nv_bfloat16 g_qcA[(size_t)S_DIM * 2 * ENC]; // gathered corr-A, unique rows
__device__ __align__(256) unsigned int g_cbmin[(size_t)S_DIM * 32];     // per-row col-block mins
__device__ float g_e2[B_DIM];
__device__ float g_q2[S_DIM];
__device__ float g_maxg[B_DIM];
__device__ unsigned char g_grp[B_DIM];
// dedup machinery
__device__ int g_present[B_DIM];
__device__ int g_uslot[B_DIM];     // b -> unique slot
__device__ int g_uidxs[S_DIM];     // slot -> b
__device__ int g_nuniq;
__device__ float g_res[S_DIM];     // per-slot result

// ------------------------------------------------------------------
// Base-ISA PTX helpers (harness compiles via compute_103: NO 'a' features)
// ------------------------------------------------------------------
__device__ __forceinline__ uint32_t smem_u32(const void* p) {
    uint32_t a;
    asm("{ .reg .u64 t; cvta.to.shared.u64 t, %1; cvt.u32.u64 %0, t; }"
        : "=r"(a) : "l"(p));
    return a;
}
__device__ __forceinline__ float tf32_rn(float x) {
    uint32_t u;
    asm("cvt.rna.tf32.f32 %0, %1;" : "=r"(u) : "f"(x));
    return __uint_as_float(u);
}
__device__ __forceinline__ void cp16(uint32_t dst, const void* src) {
    asm volatile("cp.async.cg.shared.global [%0], [%1], 16;" :: "r"(dst), "l"(src));
}
__device__ __forceinline__ void ldsm4(uint32_t* r, uint32_t addr) {
    asm volatile("ldmatrix.sync.aligned.m8n8.x4.shared.b16 {%0,%1,%2,%3}, [%4];"
                 : "=r"(r[0]), "=r"(r[1]), "=r"(r[2]), "=r"(r[3]) : "r"(addr));
}
__device__ __forceinline__ void mma_tf32(float* c, const uint32_t* a, const uint32_t* b) {
    asm volatile(
        "mma.sync.aligned.m16n8k8.row.col.f32.tf32.tf32.f32 "
        "{%0,%1,%2,%3}, {%4,%5,%6,%7}, {%8,%9}, {%0,%1,%2,%3};"
        : "+f"(c[0]), "+f"(c[1]), "+f"(c[2]), "+f"(c[3])
        : "r"(a[0]), "r"(a[1]), "r"(a[2]), "r"(a[3]), "r"(b[0]), "r"(b[1]));
}
__device__ __forceinline__ void mma_bf16(float* c, const uint32_t* a, const uint32_t* b) {
    asm volatile(
        "mma.sync.aligned.m16n8k16.row.col.f32.bf16.bf16.f32 "
        "{%0,%1,%2,%3}, {%4,%5,%6,%7}, {%8,%9}, {%0,%1,%2,%3};"
        : "+f"(c[0]), "+f"(c[1]), "+f"(c[2]), "+f"(c[3])
        : "r"(a[0]), "r"(a[1]), "r"(a[2]), "r"(a[3]), "r"(b[0]), "r"(b[1]));
}
#define SWZ(o) ((o) ^ (((o) >> 3) & 0x70))

// ------------------------------------------------------------------
// Kernel 0: init cbmin table + dedup state
// ------------------------------------------------------------------
__global__ void init_kernel() {
    int i = blockIdx.x * blockDim.x + threadIdx.x;   // 65536 threads
    uint4 ff = make_uint4(0xFFFFFFFFu, 0xFFFFFFFFu, 0xFFFFFFFFu, 0xFFFFFFFFu);
    reinterpret_cast<uint4*>(g_cbmin)[i] = ff;
    if (i < B_DIM) g_present[i] = 0;
    if (i == 0) g_nuniq = 0;
}

// ------------------------------------------------------------------
// Kernel 1: e2, argmax/max, tf32 + bf16 splits.  One block per b-row.
// ------------------------------------------------------------------
__global__ void prep_kernel(const float* __restrict__ enc,
                            const float* __restrict__ cat) {
    int b = blockIdx.x;
    int t = threadIdx.x;

    float v  = enc[(size_t)b * ENC + t];
    float hi = tf32_rn(v);
    float lo = v - hi;
    g_ehi[(size_t)b * ENC + t] = hi;
    __nv_bfloat16 h16 = __float2bfloat16(hi);
    __nv_bfloat16 l16 = __float2bfloat16(lo);
    g_ecA[(size_t)b * 2 * ENC + t]       = h16;
    g_ecA[(size_t)b * 2 * ENC + ENC + t] = l16;
    g_ecB[(size_t)b * 2 * ENC + t]       = l16;
    g_ecB[(size_t)b * 2 * ENC + ENC + t] = h16;

    float sq = v * v;
    #pragma unroll
    for (int o = 16; o > 0; o >>= 1) sq += __shfl_xor_sync(0xFFFFFFFFu, sq, o);

    __shared__ float ws[8];
    if ((t & 31) == 0) ws[t >> 5] = sq;
    __syncthreads();
    if (t == 0) {
        float s = 0.f;
        #pragma unroll
        for (int i = 0; i < 8; i++) s += ws[i];
        g_e2[b] = s;
    }

    if (t < 32) {
        float mv = -1e30f;
        int   mi = 0x7FFFFFFF;
        if (t < C_DIM) { mv = cat[(size_t)b * C_DIM + t]; mi = t; }
        #pragma unroll
        for (int o = 16; o > 0; o >>= 1) {
            float ov = __shfl_xor_sync(0xFFFFFFFFu, mv, o);
            int   oi = __shfl_xor_sync(0xFFFFFFFFu, mi, o);
            if (ov > mv || (ov == mv && oi < mi)) { mv = ov; mi = oi; }
        }
        if (t == 0) { g_maxg[b] = mv; g_grp[b] = (unsigned char)mi; }
    }
}

// ------------------------------------------------------------------
// Kernel 1b: mark unique idx values, assign slots
// (slot order is replay-nondeterministic; final output is gathered
//  through g_uslot so d_out is deterministic)
// ------------------------------------------------------------------
__global__ void mark_kernel(const int* __restrict__ idxs) {
    int s = blockIdx.x * blockDim.x + threadIdx.x;
    if (s < S_DIM) {
        int idx = idxs[s];
        if (atomicCAS(&g_present[idx], 0, 1) == 0) {
            int slot = atomicAdd(&g_nuniq, 1);
            g_uslot[idx]  = slot;
            g_uidxs[slot] = idx;
        }
    }
}

// ------------------------------------------------------------------
// Kernel 2: gather unique q rows (tf32 + corrA) + q2
// ------------------------------------------------------------------
__global__ void gather_kernel() {
    int slot = blockIdx.x, t = threadIdx.x;   // 64 threads
    if (slot >= g_nuniq) return;
    int idx = g_uidxs[slot];
    const float4* sh = reinterpret_cast<const float4*>(&g_ehi[(size_t)idx * ENC]);
    float4* dh = reinterpret_cast<float4*>(&g_qhi[(size_t)slot * ENC]);
    dh[t] = sh[t];
    const uint4* sc = reinterpret_cast<const uint4*>(&g_ecA[(size_t)idx * 2 * ENC]);
    uint4* dc = reinterpret_cast<uint4*>(&g_qcA[(size_t)slot * 2 * ENC]);
    dc[t] = sc[t];
    if (t == 0) g_q2[slot] = g_e2[idx];
}

// ------------------------------------------------------------------
// Kernel 3: mixed tf32 + bf16 GEMM -> d2 over UNIQUE rows only.
// R9 config: 256 threads, warp grid 2(M) x 4(N), warp tile 64x64.
// Early exit for M-tiles beyond the unique count.
// ------------------------------------------------------------------
#define BM 128
#define BN 256
#define NCHUNK 8
#define AF32_OFF 0
#define ACOR_OFF (128 * 128)                    // 16 KB
#define BF32_OFF (2 * 128 * 128)                // 32 KB
#define BCOR_OFF (BF32_OFF + 256 * 128)         // +32 KB
#define STAGE    (BCOR_OFF + 256 * 128)         // 96 KB
#define GEMM_SMEM (2 * STAGE)                   // 192 KB

__device__ __forceinline__ void load_stage(uint32_t st, int brow, int bcol,
                                           int c, int tid) {
    const char* qcA = reinterpret_cast<const char*>(g_qcA);
    const char* ecB = reinterpret_cast<const char*>(g_ecB);
    #pragma unroll
    for (int it = 0; it < 4; ++it) {
        int i = tid + it * 256;
        int r = i >> 3, ch = i & 7;
        uint32_t off = SWZ((uint32_t)(r * 128 + ch * 16));
        cp16(st + AF32_OFF + off, g_qhi + (size_t)(brow + r) * ENC + c * 32 + ch * 4);
        cp16(st + ACOR_OFF + off, qcA + (size_t)(brow + r) * 1024 + c * 128 + ch * 16);
    }
    #pragma unroll
    for (int it = 0; it < 8; ++it) {
        int i = tid + it * 256;
        int r = i >> 3, ch = i & 7;
        uint32_t off = SWZ((uint32_t)(r * 128 + ch * 16));
        cp16(st + BF32_OFF + off, g_ehi + (size_t)(bcol + r) * ENC + c * 32 + ch * 4);
        cp16(st + BCOR_OFF + off, ecB + (size_t)(bcol + r) * 1024 + c * 128 + ch * 16);
    }
    asm volatile("cp.async.commit_group;" ::: "memory");
}

__global__ __launch_bounds__(256, 1)
void dist_gemm_mma() {
    const int brow = blockIdx.y * BM;
    if (brow >= g_nuniq) return;      // M-tile beyond unique rows

    extern __shared__ char dsm_raw[];
    __shared__ float e2s[BN];
    __shared__ float q2s[BM];

    const int tid    = threadIdx.x;
    const int lane   = tid & 31;
    const int wid    = tid >> 5;
    const int warp_m = wid & 1;
    const int warp_n = wid >> 1;
    const int bcol   = blockIdx.x * BN;

    const uint32_t dsm = smem_u32(dsm_raw);

    for (int i = tid; i < BN; i += 256) e2s[i] = g_e2[bcol + i];
    for (int i = tid; i < BM; i += 256) q2s[i] = g_q2[brow + i];

    float acc[4][8][4];
    #pragma unroll
    for (int im = 0; im < 4; im++)
        #pragma unroll
        for (int j = 0; j < 8; j++)
            #pragma unroll
            for (int v = 0; v < 4; v++) acc[im][j][v] = 0.f;

    const int a_row = warp_m * 64 + (lane & 15);
    const int a_kb  = (lane >> 4) << 4;
    const int b_row = warp_n * 64 + ((lane >> 4) << 3) + (lane & 7);
    const int b_kb  = ((lane >> 3) & 1) << 4;

    load_stage(dsm,         brow, bcol, 0, tid);
    load_stage(dsm + STAGE, brow, bcol, 1, tid);

    #pragma unroll
    for (int c = 0; c < NCHUNK; ++c) {
        if (c == NCHUNK - 1) asm volatile("cp.async.wait_group 0;" ::: "memory");
        else                 asm volatile("cp.async.wait_group 1;" ::: "memory");
        __syncthreads();

        const uint32_t st = dsm + (c & 1) * STAGE;

        #pragma unroll
        for (int ks = 0; ks < 4; ++ks) {
            uint32_t ahi[4][4], aco[4][4], bhi[8][2], bco[8][2];
            #pragma unroll
            for (int im = 0; im < 4; ++im) {
                uint32_t off = SWZ((uint32_t)((a_row + im * 16) * 128 + ks * 32 + a_kb));
                ldsm4(ahi[im], st + AF32_OFF + off);
                ldsm4(aco[im], st + ACOR_OFF + off);
            }
            #pragma unroll
            for (int jn = 0; jn < 4; ++jn) {
                uint32_t off = SWZ((uint32_t)((b_row + jn * 16) * 128 + ks * 32 + b_kb));
                uint32_t rh[4], rc[4];
                ldsm4(rh, st + BF32_OFF + off);
                ldsm4(rc, st + BCOR_OFF + off);
                bhi[2 * jn][0] = rh[0]; bhi[2 * jn][1] = rh[1];
                bhi[2 * jn + 1][0] = rh[2]; bhi[2 * jn + 1][1] = rh[3];
                bco[2 * jn][0] = rc[0]; bco[2 * jn][1] = rc[1];
                bco[2 * jn + 1][0] = rc[2]; bco[2 * jn + 1][1] = rc[3];
            }
            #pragma unroll
            for (int im = 0; im < 4; ++im)
                #pragma unroll
                for (int j = 0; j < 8; ++j) {
                    mma_tf32(acc[im][j], ahi[im], bhi[j]);
                    mma_bf16(acc[im][j], aco[im], bco[j]);
                }
        }
        __syncthreads();
        if (c + 2 < NCHUNK)
            load_stage(dsm + (c & 1) * STAGE, brow, bcol, c + 2, tid);
    }

    // Epilogue: d2 = max(q2 + e2 - 2*acc, 0), plain stores, per-row block mins
    #pragma unroll
    for (int im = 0; im < 4; ++im) {
        const int r0 = warp_m * 64 + im * 16 + (lane >> 2);
        const float q2a = q2s[r0];
        const float q2b = q2s[r0 + 8];
        uint32_t mna = 0xFFFFFFFFu, mnb = 0xFFFFFFFFu;
        #pragma unroll
        for (int j = 0; j < 8; ++j) {
            const int cl = warp_n * 64 + j * 8 + 2 * (lane & 3);
            const float e0 = e2s[cl], e1 = e2s[cl + 1];
            float2 oa, ob;
            oa.x = fmaxf(fmaf(-2.f, acc[im][j][0], q2a + e0), 0.f);
            oa.y = fmaxf(fmaf(-2.f, acc[im][j][1], q2a + e1), 0.f);
            ob.x = fmaxf(fmaf(-2.f, acc[im][j][2], q2b + e0), 0.f);
            ob.y = fmaxf(fmaf(-2.f, acc[im][j][3], q2b + e1), 0.f);
            mna = min(mna, min(__float_as_uint(oa.x), __float_as_uint(oa.y)));
            mnb = min(mnb, min(__float_as_uint(ob.x), __float_as_uint(ob.y)));
            *reinterpret_cast<float2*>(&g_d2[(size_t)(brow + r0) * B_DIM + bcol + cl]) = oa;
            *reinterpret_cast<float2*>(&g_d2[(size_t)(brow + r0 + 8) * B_DIM + bcol + cl]) = ob;
        }
        mna = min(mna, __shfl_xor_sync(0xFFFFFFFFu, mna, 1));
        mna = min(mna, __shfl_xor_sync(0xFFFFFFFFu, mna, 2));
        mnb = min(mnb, __shfl_xor_sync(0xFFFFFFFFu, mnb, 1));
        mnb = min(mnb, __shfl_xor_sync(0xFFFFFFFFu, mnb, 2));
        if ((lane & 3) == 0) {
            atomicMin(&g_cbmin[(size_t)(brow + r0) * 32 + blockIdx.x], mna);
            atomicMin(&g_cbmin[(size_t)(brow + r0 + 8) * 32 + blockIdx.x], mnb);
        }
    }
}

// ------------------------------------------------------------------
// Kernel 4: bound-from-GEMM select over UNIQUE rows. Exact.
// Writes per-slot result g_res[slot]; scatter kernel fans out.
// ------------------------------------------------------------------
#define CAND_CAP 2048

__global__ __launch_bounds__(256)
void select_kernel() {
    const int s    = blockIdx.x;           // unique slot
    if (s >= g_nuniq) return;
    const int tid  = threadIdx.x;
    const int lane = tid & 31;
    const int wid  = tid >> 5;

    __shared__ uint32_t cand_v[CAND_CAP];     // 8 KB
    __shared__ uint32_t cand_i[CAND_CAP];     // 8 KB
    __shared__ uint32_t wred[8];
    __shared__ uint32_t sh_m;
    __shared__ uint32_t sh_B;
    __shared__ uint32_t sh_kbits;
    __shared__ int counts[C_DIM];

    // Bound from GEMM by-product: max of 32 block mins
    if (wid == 0) {
        uint32_t b = g_cbmin[(size_t)s * 32 + lane];
        #pragma unroll
        for (int o = 16; o > 0; o >>= 1)
            b = max(b, __shfl_xor_sync(0xFFFFFFFFu, b, o));
        if (lane == 0) sh_B = b;
    }

    // Load row into registers (coalesced uint4)
    const uint4* row4 = reinterpret_cast<const uint4*>(g_d2 + (size_t)s * B_DIM);
    uint4 v[8];
    #pragma unroll
    for (int k = 0; k < 8; k++) v[k] = row4[tid + k * 256];

    if (tid == 0) sh_m = 0;
    __syncthreads();
    uint32_t B = sh_B;

    // count of values strictly below X (fallback path only)
    auto count_lt = [&](uint32_t X) -> int {
        int c = 0;
        #pragma unroll
        for (int k = 0; k < 8; k++)
            c += (int)(v[k].x < X) + (int)(v[k].y < X) +
                 (int)(v[k].z < X) + (int)(v[k].w < X);
        #pragma unroll
        for (int o = 16; o > 0; o >>= 1)
            c += __shfl_xor_sync(0xFFFFFFFFu, c, o);
        if (lane == 0) wred[wid] = (uint32_t)c;
        __syncthreads();
        int t = 0;
        #pragma unroll
        for (int w = 0; w < 8; w++) t += (int)wred[w];
        __syncthreads();
        return t;
    };

    // Collect directly; expected m ~ 130 on first pass.
    int m = 0;
    bool direct = false;
    uint32_t direct_kbits = 0;
    for (int attempt = 0; attempt < 72; ++attempt) {
        #pragma unroll
        for (int k = 0; k < 8; k++) {
            uint32_t vv[4] = {v[k].x, v[k].y, v[k].z, v[k].w};
            #pragma unroll
            for (int j = 0; j < 4; j++) {
                if (vv[j] < B) {
                    uint32_t p = atomicAdd(&sh_m, 1u);
                    if (p < CAND_CAP) {
                        cand_v[p] = vv[j];
                        cand_i[p] = 4u * (uint32_t)(tid + k * 256) + (uint32_t)j;
                    }
                }
            }
        }
        __syncthreads();
        m = (int)sh_m;
        if (m >= 26 && m <= CAND_CAP) break;

        if (m < 26) {
            B += (1u << 20);
            if (B >= 0x7F800000u) B = 0x7F800001u;
        } else {
            uint32_t lo = 0;
            int cnt = m;
            while (cnt > CAND_CAP) {
                uint32_t mid = lo + ((B - lo) >> 1);
                if (mid == lo) { direct = true; direct_kbits = lo; break; }
                int c2 = count_lt(mid);
                if (c2 >= 26) { B = mid; cnt = c2; }
                else          { lo = mid; }
            }
            if (direct) break;
        }
        if (tid == 0) sh_m = 0;
        __syncthreads();
    }

    if (tid < C_DIM) counts[tid] = 0;
    __syncthreads();

    // Exact rank-25 among the m candidates
    if (!direct) {
        m = min(m, CAND_CAP);
        for (int i = tid; i < m; i += 256) {
            uint32_t vi = cand_v[i];
            int l = 0, e = 0;
            for (int j = 0; j < m; j++) {
                uint32_t vj = cand_v[j];
                l += (vj < vi);
                e += (vj == vi);
            }
            if (l <= K_RANK && K_RANK < l + e) sh_kbits = vi;
        }
    } else if (tid == 0) {
        sh_kbits = direct_kbits;
    }
    __syncthreads();
    const uint32_t kbits = sh_kbits;

    // Bincount of neighbours (v < kbits)
    if (!direct) {
        for (int i = tid; i < m; i += 256) {
            if (cand_v[i] < kbits)
                atomicAdd(&counts[g_grp[cand_i[i]]], 1);
        }
    } else {
        #pragma unroll
        for (int k = 0; k < 8; k++) {
            uint32_t vv[4] = {v[k].x, v[k].y, v[k].z, v[k].w};
            #pragma unroll
            for (int j = 0; j < 4; j++) {
                if (vv[j] < kbits)
                    atomicAdd(&counts[g_grp[4 * (tid + k * 256) + j]], 1);
            }
        }
    }
    __syncthreads();

    if (tid == 0) {
        int n = 0;
        #pragma unroll
        for (int c = 0; c < C_DIM; c++) n += counts[c];
        float inv = 1.0f / (float)n;
        float purity = 0.f;
        #pragma unroll
        for (int c = 0; c < C_DIM; c++) {
            float p = (float)counts[c] * inv;
            purity -= p * logf(p + 1e-5f);
        }
        g_res[s] = purity * g_maxg[g_uidxs[s]];
    }
}

// ------------------------------------------------------------------
// Kernel 5: scatter per-slot results to all duplicate samples
// ------------------------------------------------------------------
__global__ void scatter_kernel(const int* __restrict__ idxs,
                               float* __restrict__ out) {
    int s = blockIdx.x * blockDim.x + threadIdx.x;
    if (s < S_DIM) out[s] = g_res[g_uslot[idxs[s]]];
}

// ------------------------------------------------------------------
// Launch
// ------------------------------------------------------------------
extern "C" void kernel_launch(void* const* d_in, const int* in_sizes, int n_in,
                              void* d_out, int out_size) {
    const float* enc  = (const float*)d_in[0];
    const float* cat  = (const float*)d_in[1];
    const int*   idxs = (const int*)d_in[2];
    float* out = (float*)d_out;

    static bool attr_done = false;
    if (!attr_done) {
        cudaFuncSetAttribute(dist_gemm_mma,
                             cudaFuncAttributeMaxDynamicSharedMemorySize, GEMM_SMEM);
        attr_done = true;
    }

    init_kernel<<<256, 256>>>();
    prep_kernel<<<B_DIM, 256>>>(enc, cat);
    mark_kernel<<<S_DIM / 256, 256>>>(idxs);
    gather_kernel<<<S_DIM, 64>>>();

    dim3 grid(B_DIM / BN, S_DIM / BM);
    dist_gemm_mma<<<grid, 256, GEMM_SMEM>>>();

    select_kernel<<<S_DIM, 256>>>();
    scatter_kernel<<<S_DIM / 256, 256>>>(idxs, out);
}